// round 17
// baseline (speedup 1.0000x reference)
#include <cuda_runtime.h>
#include <cuda_fp16.h>
#include <math.h>

#define MDIM 128        // N_COMBOS (dual dim)
#define NDIM 512        // N_STRUCTS (primal dim)
#define HID  20
#define NITER 60
#define CONTROLF 10.0f
#define RCAP 40
#define CCAP 16
#define CCAPH 12
#define RJJ  (RCAP/4)
#define CJJ  (CCAP/4)
#define PB   2          // problems (4-row groups) per CTA
#define RROWS (4*PB)    // batch rows per CTA

// Raw adjacency lists (by actual id).
__device__ int            g_csr_rawn[MDIM];
__device__ unsigned short g_csr_raw[MDIM * RCAP];
__device__ int            g_csc_rawn[NDIM];
__device__ unsigned short g_csc_raw[NDIM * CCAP];
__device__ int            g_csc_rawn2[2 * NDIM];
__device__ unsigned short g_csc_raw2[2 * NDIM * CCAPH];

// Owner permutations (slot -> actual id), sorted by nnz for warp balance.
__device__ int g_rm[MDIM];
__device__ int g_rn[NDIM];

// Packed, transposed (by OWNER SLOT), zero-slot-padded index lists.
__device__ int     g_csr_cnt[MDIM];
__device__ ushort4 g_csr_pk[RJJ * MDIM];
__device__ int     g_csc_cnt[NDIM];
__device__ uchar4  g_csc_pk[CJJ * NDIM];
__device__ float   g_tau;

// ---------------------------------------------------------------------------
// Kernel 0a: raw structure build, wide + latency-hidden. 24 blocks x 128 thr.
// ---------------------------------------------------------------------------
__global__ void build_kernel(const float* __restrict__ S) {
    const int t = threadIdx.x;
    const int b = blockIdx.x;

    if (b < 8) {
        const int h = b >> 2;
        const int n = (b & 3) * 128 + t;
        const int base = 64 * h;
        int cnt = 0;
        for (int c0 = 0; c0 < 64; c0 += 16) {
            float vals[16];
            #pragma unroll
            for (int i = 0; i < 16; i++) vals[i] = S[(base + c0 + i) * NDIM + n];
            #pragma unroll
            for (int i = 0; i < 16; i++) {
                if (vals[i] != 0.0f) {
                    if (cnt < CCAPH)
                        g_csc_raw2[(h * NDIM + n) * CCAPH + cnt] =
                            (unsigned short)(base + c0 + i);
                    cnt++;
                }
            }
        }
        g_csc_rawn2[h * NDIM + n] = cnt < CCAPH ? cnt : CCAPH;
    } else {
        const int lane = t & 31;
        const int w    = t >> 5;
        const float4* S4 = reinterpret_cast<const float4*>(S);
        for (int rr = 0; rr < 2; rr++) {
            const int m = (b - 8) * 8 + w * 2 + rr;
            float4 v[4];
            #pragma unroll
            for (int q = 0; q < 4; q++) v[q] = S4[m * 128 + q * 32 + lane];
            int c = 0;
            #pragma unroll
            for (int q = 0; q < 4; q++) {
                const float vv[4] = {v[q].x, v[q].y, v[q].z, v[q].w};
                #pragma unroll
                for (int comp = 0; comp < 4; comp++) {
                    const bool nz = (vv[comp] != 0.0f);
                    const unsigned mask = __ballot_sync(0xffffffffu, nz);
                    if (nz) {
                        const int pos = c + __popc(mask & ((1u << lane) - 1u));
                        if (pos < RCAP)
                            g_csr_raw[m * RCAP + pos] =
                                (unsigned short)(q * 128 + lane * 4 + comp);
                    }
                    c += __popc(mask);
                }
            }
            if (lane == 0) g_csr_rawn[m] = c < RCAP ? c : RCAP;
        }
    }
}

// ---------------------------------------------------------------------------
// Kernel 0b: concat CSC halves, counting-sort, repack, power iteration -> tau.
// ---------------------------------------------------------------------------
__global__ void __launch_bounds__(512) pack_power_kernel() {
    const int t = threadIdx.x;

    {
        const int L0 = g_csc_rawn2[t];
        const int L1 = g_csc_rawn2[NDIM + t];
        int L = L0 + L1; if (L > CCAP) L = CCAP;
        for (int j = 0; j < L0 && j < CCAP; j++)
            g_csc_raw[t * CCAP + j] = g_csc_raw2[t * CCAPH + j];
        for (int j = 0; j < L1 && L0 + j < CCAP; j++)
            g_csc_raw[t * CCAP + L0 + j] = g_csc_raw2[(NDIM + t) * CCAPH + j];
        g_csc_rawn[t] = L;
    }
    __syncthreads();

    __shared__ int r_hist[64];
    __shared__ int c_hist[64];
    if (t < 64) { r_hist[t] = 0; c_hist[t] = 0; }
    __syncthreads();

    if (t < MDIM) atomicAdd(&r_hist[g_csr_rawn[t]], 1);
    atomicAdd(&c_hist[g_csc_rawn[t]], 1);
    __syncthreads();

    if (t == 0) { int s = 0; for (int k = 0; k < 64; k++) { int x = r_hist[k]; r_hist[k] = s; s += x; } }
    if (t == 1) { int s = 0; for (int k = 0; k < 64; k++) { int x = c_hist[k]; c_hist[k] = s; s += x; } }
    __syncthreads();

    if (t < MDIM) {
        const int pos = atomicAdd(&r_hist[g_csr_rawn[t]], 1);
        g_rm[pos] = t;
    }
    {
        const int pos = atomicAdd(&c_hist[g_csc_rawn[t]], 1);
        g_rn[pos] = t;
    }
    __syncthreads();

    if (t < MDIM) {
        const int m = g_rm[t];
        const int L = g_csr_rawn[m];
        unsigned short* pk = reinterpret_cast<unsigned short*>(g_csr_pk);
        for (int j = 0; j < L; j++)
            pk[((j >> 2) * MDIM + t) * 4 + (j & 3)] = g_csr_raw[m * RCAP + j];
        const int cnt4 = (L + 3) >> 2;
        for (int j = L; j < cnt4 * 4; j++)
            pk[((j >> 2) * MDIM + t) * 4 + (j & 3)] = (unsigned short)NDIM;
        g_csr_cnt[t] = cnt4;
    }
    {
        const int n = g_rn[t];
        const int L = g_csc_rawn[n];
        unsigned char* pk = reinterpret_cast<unsigned char*>(g_csc_pk);
        for (int j = 0; j < L; j++)
            pk[((j >> 2) * NDIM + t) * 4 + (j & 3)] = (unsigned char)g_csc_raw[n * CCAP + j];
        const int cnt4 = (L + 3) >> 2;
        for (int j = L; j < cnt4 * 4; j++)
            pk[((j >> 2) * NDIM + t) * 4 + (j & 3)] = (unsigned char)MDIM;
        g_csc_cnt[t] = cnt4;
    }
    __syncthreads();

    __shared__ float v[NDIM + 1];
    __shared__ float p[MDIM + 1];
    __shared__ float red[16];

    v[t] = 1.0f;
    if (t == 0) { v[NDIM] = 0.0f; p[MDIM] = 0.0f; }
    __syncthreads();

    const int myn  = g_rn[t];
    const int mym  = (t < MDIM) ? g_rm[t] : 0;
    const int ccnt = g_csc_cnt[t];
    float Lsq = 0.0f;

    for (int it = 0; it <= 30; it++) {
        if (t < MDIM) {
            float a = 0.0f;
            const int rc = g_csr_cnt[t];
            for (int jj = 0; jj < rc; jj++) {
                const ushort4 id = g_csr_pk[jj * MDIM + t];
                a += v[id.x] + v[id.y] + v[id.z] + v[id.w];
            }
            p[mym] = a;
        }
        __syncthreads();
        float a = v[myn];
        for (int jj = 0; jj < ccnt; jj++) {
            const uchar4 id = g_csc_pk[jj * NDIM + t];
            a += p[id.x] + p[id.y] + p[id.z] + p[id.w];
        }

        float s = (it == 30) ? (a * v[myn]) : (a * a);
        #pragma unroll
        for (int o = 16; o > 0; o >>= 1) s += __shfl_xor_sync(0xffffffffu, s, o);
        if ((t & 31) == 0) red[t >> 5] = s;
        __syncthreads();
        float tot = 0.0f;
        #pragma unroll
        for (int ww = 0; ww < 16; ww++) tot += red[ww];

        if (it == 30) { Lsq = tot; break; }
        v[myn] = a / sqrtf(tot);
        __syncthreads();
    }

    if (t == 0) g_tau = 0.9f / sqrtf(Lsq);
}

// ---------------------------------------------------------------------------
__device__ __forceinline__ float4 f4add(float4 a, float4 b) {
    return make_float4(a.x + b.x, a.y + b.y, a.z + b.z, a.w + b.w);
}
__device__ __forceinline__ __half2 ash2(unsigned u) {
    return *reinterpret_cast<const __half2*>(&u);
}
__device__ __forceinline__ unsigned h2u(__half2 h) {
    return *reinterpret_cast<const unsigned*>(&h);
}
__device__ __forceinline__ uint2 packh4(float4 v) {
    const __half2 lo = __floats2half2_rn(v.x, v.y);
    const __half2 hi = __floats2half2_rn(v.z, v.w);
    return make_uint2(h2u(lo), h2u(hi));
}
__device__ __forceinline__ float4 unpackh4(uint2 v) {
    const float2 lo = __half22float2(ash2(v.x));
    const float2 hi = __half22float2(ash2(v.y));
    return make_float4(lo.x, lo.y, hi.x, hi.y);
}
__device__ __forceinline__ void accq(float4& a, uint2 v0, uint2 v1,
                                     uint2 v2, uint2 v3) {
    const __half2 lo = __hadd2(__hadd2(ash2(v0.x), ash2(v1.x)),
                               __hadd2(ash2(v2.x), ash2(v3.x)));
    const __half2 hi = __hadd2(__hadd2(ash2(v0.y), ash2(v1.y)),
                               __hadd2(ash2(v2.y), ash2(v3.y)));
    const float2 flo = __half22float2(lo);
    const float2 fhi = __half22float2(hi);
    a.x += flo.x; a.y += flo.y; a.z += fhi.x; a.w += fhi.y;
}
__device__ __forceinline__ void accp(float4& a,
                                     uint2 v0, uint2 v1, uint2 v2, uint2 v3,
                                     uint2 w0, uint2 w1, uint2 w2, uint2 w3) {
    const __half2 lo = __hadd2(
        __hadd2(__hadd2(ash2(v0.x), ash2(v1.x)), __hadd2(ash2(v2.x), ash2(v3.x))),
        __hadd2(__hadd2(ash2(w0.x), ash2(w1.x)), __hadd2(ash2(w2.x), ash2(w3.x))));
    const __half2 hi = __hadd2(
        __hadd2(__hadd2(ash2(v0.y), ash2(v1.y)), __hadd2(ash2(v2.y), ash2(v3.y))),
        __hadd2(__hadd2(ash2(w0.y), ash2(w1.y)), __hadd2(ash2(w2.y), ash2(w3.y))));
    const float2 flo = __half22float2(lo);
    const float2 fhi = __half22float2(hi);
    a.x += flo.x; a.y += flo.y; a.z += fhi.x; a.w += fhi.y;
}

// ---------------------------------------------------------------------------
// Kernel 1: fused MLP + PDHG. TWO independent 4-row problems per CTA,
// 128 threads. Each thread runs dual+primal for both problems (2x ILP);
// index lists shared; per-problem fp16 gather arrays.
// ---------------------------------------------------------------------------
__global__ void __launch_bounds__(128) solve_kernel(
    const float* __restrict__ X,
    const float* __restrict__ W1, const float* __restrict__ B1,
    const float* __restrict__ W2, const float* __restrict__ B2,
    const float* __restrict__ W3, const float* __restrict__ B3,
    const float* __restrict__ W4, const float* __restrict__ B4,
    float* __restrict__ out)
{
    const int row0 = blockIdx.x * RROWS;
    const int t    = threadIdx.x;   // 0..127

    __shared__ float4 bx_sh[PB][MDIM];
    __shared__ uint2  xbH[PB][NDIM + 1];
    __shared__ uint2  lam1H[PB][MDIM + 1];
    __shared__ float  h_sh[4][HID + 4];
    __shared__ float4 red[PB][4];

    #pragma unroll
    for (int pb = 0; pb < PB; pb++) {
        float4 v;
        v.x = X[(row0 + pb * 4 + 0) * MDIM + t];
        v.y = X[(row0 + pb * 4 + 1) * MDIM + t];
        v.z = X[(row0 + pb * 4 + 2) * MDIM + t];
        v.w = X[(row0 + pb * 4 + 3) * MDIM + t];
        bx_sh[pb][t] = v;
    }
    if (t == 0) {
        #pragma unroll
        for (int pb = 0; pb < PB; pb++) {
            xbH[pb][NDIM]   = make_uint2(0u, 0u);
            lam1H[pb][MDIM] = make_uint2(0u, 0u);
        }
    }
    const int mym = g_rm[t];
    int rn[4];
    #pragma unroll
    for (int k = 0; k < 4; k++) rn[k] = g_rn[t + 128 * k];
    __syncthreads();

    float4 z[PB][4], x[PB][4], lam2[PB][4];
    uint2  xbp[PB][4];

    // ---- MLP + init, sequential per problem (one-time cost) ----
    for (int pb = 0; pb < PB; pb++) {
        if (t < 4 * HID) {
            const int r = t / HID, i = t % HID;
            float a = B1[i];
            for (int k = 0; k < MDIM; k++)
                a += ((const float*)&bx_sh[pb][k])[r] * W1[k * HID + i];
            h_sh[r][i] = tanhf(a);
        }
        __syncthreads();
        {
            float a = 0.0f;
            if (t < 4 * HID) {
                const int r = t / HID, i = t % HID;
                a = B2[i];
                #pragma unroll
                for (int k = 0; k < HID; k++) a += h_sh[r][k] * W2[k * HID + i];
                a = tanhf(a);
            }
            __syncthreads();
            if (t < 4 * HID) h_sh[t / HID][t % HID] = a;
            __syncthreads();
            if (t < 4 * HID) {
                const int r = t / HID, i = t % HID;
                a = B3[i];
                #pragma unroll
                for (int k = 0; k < HID; k++) a += h_sh[r][k] * W3[k * HID + i];
                a = tanhf(a);
            }
            __syncthreads();
            if (t < 4 * HID) h_sh[t / HID][t % HID] = a;
            __syncthreads();
        }
        #pragma unroll
        for (int k = 0; k < 4; k++) {
            const int n = rn[k];
            const float b4v = B4[n];
            float4 a = make_float4(b4v, b4v, b4v, b4v);
            #pragma unroll
            for (int j = 0; j < HID; j++) {
                const float w = W4[j * NDIM + n];
                a.x += h_sh[0][j] * w;
                a.y += h_sh[1][j] * w;
                a.z += h_sh[2][j] * w;
                a.w += h_sh[3][j] * w;
            }
            z[pb][k] = a;
            x[pb][k] = make_float4(fmaxf(a.x, 0.f), fmaxf(a.y, 0.f),
                                   fmaxf(a.z, 0.f), fmaxf(a.w, 0.f));
            lam2[pb][k] = make_float4(0.f, 0.f, 0.f, 0.f);
            xbp[pb][k] = packh4(x[pb][k]);
            xbH[pb][n] = xbp[pb][k];
        }
        __syncthreads();
    }

    const float tau = g_tau;                  // sig == tau
    float4 lam1r[PB], taub[PB];
    #pragma unroll
    for (int pb = 0; pb < PB; pb++) {
        lam1r[pb] = make_float4(0.f, 0.f, 0.f, 0.f);
        lam1H[pb][mym] = make_uint2(0u, 0u);
        const float4 b4 = bx_sh[pb][mym];
        taub[pb] = make_float4(tau * b4.x, tau * b4.y, tau * b4.z, tau * b4.w);
    }
    const int rcnt = g_csr_cnt[t];
    int cc[4];
    #pragma unroll
    for (int k = 0; k < 4; k++) cc[k] = g_csc_cnt[t + 128 * k];
    __syncthreads();

    // ---- PDHG mainloop (both problems advance together) ----
    for (int it = 0; it < NITER; it++) {
        // dual 1 for both problems (shared index loads, 2x ILP)
        {
            float4 acc0 = make_float4(0.f, 0.f, 0.f, 0.f);
            float4 acc1 = make_float4(0.f, 0.f, 0.f, 0.f);
            int jj = 0;
            for (; jj + 2 <= rcnt; jj += 2) {
                const ushort4 i0 = g_csr_pk[jj * MDIM + t];
                const ushort4 i1 = g_csr_pk[(jj + 1) * MDIM + t];
                accp(acc0,
                     xbH[0][i0.x], xbH[0][i0.y], xbH[0][i0.z], xbH[0][i0.w],
                     xbH[0][i1.x], xbH[0][i1.y], xbH[0][i1.z], xbH[0][i1.w]);
                accp(acc1,
                     xbH[1][i0.x], xbH[1][i0.y], xbH[1][i0.z], xbH[1][i0.w],
                     xbH[1][i1.x], xbH[1][i1.y], xbH[1][i1.z], xbH[1][i1.w]);
            }
            if (jj < rcnt) {
                const ushort4 id = g_csr_pk[jj * MDIM + t];
                accq(acc0, xbH[0][id.x], xbH[0][id.y], xbH[0][id.z], xbH[0][id.w]);
                accq(acc1, xbH[1][id.x], xbH[1][id.y], xbH[1][id.z], xbH[1][id.w]);
            }
            lam1r[0].x = fmaxf(fmaf(tau, acc0.x, lam1r[0].x) - taub[0].x, 0.f);
            lam1r[0].y = fmaxf(fmaf(tau, acc0.y, lam1r[0].y) - taub[0].y, 0.f);
            lam1r[0].z = fmaxf(fmaf(tau, acc0.z, lam1r[0].z) - taub[0].z, 0.f);
            lam1r[0].w = fmaxf(fmaf(tau, acc0.w, lam1r[0].w) - taub[0].w, 0.f);
            lam1H[0][mym] = packh4(lam1r[0]);
            lam1r[1].x = fmaxf(fmaf(tau, acc1.x, lam1r[1].x) - taub[1].x, 0.f);
            lam1r[1].y = fmaxf(fmaf(tau, acc1.y, lam1r[1].y) - taub[1].y, 0.f);
            lam1r[1].z = fmaxf(fmaf(tau, acc1.z, lam1r[1].z) - taub[1].z, 0.f);
            lam1r[1].w = fmaxf(fmaf(tau, acc1.w, lam1r[1].w) - taub[1].w, 0.f);
            lam1H[1][mym] = packh4(lam1r[1]);
        }
        // dual 2: lam2 = min(lam2 + tau*xb, 0); xb operand from packed regs
        #pragma unroll
        for (int pb = 0; pb < PB; pb++)
            #pragma unroll
            for (int k = 0; k < 4; k++) {
                const float4 xbv = unpackh4(xbp[pb][k]);
                lam2[pb][k].x = fminf(fmaf(tau, xbv.x, lam2[pb][k].x), 0.f);
                lam2[pb][k].y = fminf(fmaf(tau, xbv.y, lam2[pb][k].y), 0.f);
                lam2[pb][k].z = fminf(fmaf(tau, xbv.z, lam2[pb][k].z), 0.f);
                lam2[pb][k].w = fminf(fmaf(tau, xbv.w, lam2[pb][k].w), 0.f);
            }
        __syncthreads();

        // primal for both problems
        float4 u[PB][4];
        float4 ss[PB];
        ss[0] = make_float4(0.f, 0.f, 0.f, 0.f);
        ss[1] = make_float4(0.f, 0.f, 0.f, 0.f);
        #pragma unroll
        for (int k = 0; k < 4; k++) {
            const int cnt = cc[k];
            float4 ca0 = make_float4(0.f, 0.f, 0.f, 0.f);
            float4 ca1 = make_float4(0.f, 0.f, 0.f, 0.f);
            for (int jj = 0; jj < cnt; jj++) {
                const uchar4 id = g_csc_pk[jj * NDIM + (t + 128 * k)];
                accq(ca0, lam1H[0][id.x], lam1H[0][id.y], lam1H[0][id.z], lam1H[0][id.w]);
                accq(ca1, lam1H[1][id.x], lam1H[1][id.y], lam1H[1][id.z], lam1H[1][id.w]);
            }
            u[0][k].x = (x[0][k].x - tau * (ca0.x + lam2[0][k].x)) + tau - z[0][k].x;
            u[0][k].y = (x[0][k].y - tau * (ca0.y + lam2[0][k].y)) + tau - z[0][k].y;
            u[0][k].z = (x[0][k].z - tau * (ca0.z + lam2[0][k].z)) + tau - z[0][k].z;
            u[0][k].w = (x[0][k].w - tau * (ca0.w + lam2[0][k].w)) + tau - z[0][k].w;
            ss[0].x += u[0][k].x * u[0][k].x;
            ss[0].y += u[0][k].y * u[0][k].y;
            ss[0].z += u[0][k].z * u[0][k].z;
            ss[0].w += u[0][k].w * u[0][k].w;
            u[1][k].x = (x[1][k].x - tau * (ca1.x + lam2[1][k].x)) + tau - z[1][k].x;
            u[1][k].y = (x[1][k].y - tau * (ca1.y + lam2[1][k].y)) + tau - z[1][k].y;
            u[1][k].z = (x[1][k].z - tau * (ca1.z + lam2[1][k].z)) + tau - z[1][k].z;
            u[1][k].w = (x[1][k].w - tau * (ca1.w + lam2[1][k].w)) + tau - z[1][k].w;
            ss[1].x += u[1][k].x * u[1][k].x;
            ss[1].y += u[1][k].y * u[1][k].y;
            ss[1].z += u[1][k].z * u[1][k].z;
            ss[1].w += u[1][k].w * u[1][k].w;
        }

        // block reduce ||u||^2 per row (8 components, ILP across both)
        #pragma unroll
        for (int o = 16; o > 0; o >>= 1) {
            #pragma unroll
            for (int pb = 0; pb < PB; pb++) {
                ss[pb].x += __shfl_xor_sync(0xffffffffu, ss[pb].x, o);
                ss[pb].y += __shfl_xor_sync(0xffffffffu, ss[pb].y, o);
                ss[pb].z += __shfl_xor_sync(0xffffffffu, ss[pb].z, o);
                ss[pb].w += __shfl_xor_sync(0xffffffffu, ss[pb].w, o);
            }
        }
        if ((t & 31) == 0) {
            red[0][t >> 5] = ss[0];
            red[1][t >> 5] = ss[1];
        }
        __syncthreads();
        {
            const float tc = tau * CONTROLF;
            #pragma unroll
            for (int pb = 0; pb < PB; pb++) {
                const float4 tot = f4add(f4add(red[pb][0], red[pb][1]),
                                         f4add(red[pb][2], red[pb][3]));
                float4 sc;
                sc.x = fmaxf(0.f, 1.f - tc * rsqrtf(fmaxf(tot.x, 1e-24f)));
                sc.y = fmaxf(0.f, 1.f - tc * rsqrtf(fmaxf(tot.y, 1e-24f)));
                sc.z = fmaxf(0.f, 1.f - tc * rsqrtf(fmaxf(tot.z, 1e-24f)));
                sc.w = fmaxf(0.f, 1.f - tc * rsqrtf(fmaxf(tot.w, 1e-24f)));

                #pragma unroll
                for (int k = 0; k < 4; k++) {
                    float4 xn;
                    xn.x = fmaf(sc.x, u[pb][k].x, z[pb][k].x);
                    xn.y = fmaf(sc.y, u[pb][k].y, z[pb][k].y);
                    xn.z = fmaf(sc.z, u[pb][k].z, z[pb][k].z);
                    xn.w = fmaf(sc.w, u[pb][k].w, z[pb][k].w);
                    float4 nb;
                    nb.x = 2.f * xn.x - x[pb][k].x;
                    nb.y = 2.f * xn.y - x[pb][k].y;
                    nb.z = 2.f * xn.z - x[pb][k].z;
                    nb.w = 2.f * xn.w - x[pb][k].w;
                    x[pb][k] = xn;
                    xbp[pb][k] = packh4(nb);
                    xbH[pb][rn[k]] = xbp[pb][k];
                }
            }
        }
        __syncthreads();
    }

    #pragma unroll
    for (int pb = 0; pb < PB; pb++)
        #pragma unroll
        for (int k = 0; k < 4; k++) {
            const int n = rn[k];
            out[(row0 + pb * 4 + 0) * NDIM + n] = x[pb][k].x;
            out[(row0 + pb * 4 + 1) * NDIM + n] = x[pb][k].y;
            out[(row0 + pb * 4 + 2) * NDIM + n] = x[pb][k].z;
            out[(row0 + pb * 4 + 3) * NDIM + n] = x[pb][k].w;
        }
}

// ---------------------------------------------------------------------------
extern "C" void kernel_launch(void* const* d_in, const int* in_sizes, int n_in,
                              void* d_out, int out_size) {
    const float* X  = (const float*)d_in[0];
    const float* W1 = (const float*)d_in[1];
    const float* B1 = (const float*)d_in[2];
    const float* W2 = (const float*)d_in[3];
    const float* B2 = (const float*)d_in[4];
    const float* W3 = (const float*)d_in[5];
    const float* B3 = (const float*)d_in[6];
    const float* W4 = (const float*)d_in[7];
    const float* B4 = (const float*)d_in[8];
    const float* S  = (const float*)d_in[9];
    const int batch = in_sizes[0] / MDIM;

    build_kernel<<<24, 128>>>(S);
    pack_power_kernel<<<1, NDIM>>>();
    solve_kernel<<<batch / RROWS, 128>>>(X, W1, B1, W2, B2, W3, B3, W4, B4,
                                         (float*)d_out);
}